// round 2
// baseline (speedup 1.0000x reference)
#include <cuda_runtime.h>

// Problem constants (match reference)
#define NN 100000
#define EE 1000000
#define HH 64
#define GG 512
#define CC 2

// Scratch (no allocation allowed -> __device__ globals)
__device__ float g_xw[NN * HH];      // X @ W for current layer
__device__ float g_h[NN * HH];       // hidden state / aggregation target
__device__ float g_deg[NN];
__device__ float g_dinv[NN];
__device__ float g_selfc[NN];        // 2 * dinv^2
__device__ float g_norm[EE];
__device__ float g_pooled[GG * HH];
__device__ float g_cnt[GG];

// ---------------------------------------------------------------------------
// Zero the per-call accumulators (deg, pooled, cnt)
// ---------------------------------------------------------------------------
__global__ void init_kernel(int n_nodes) {
    int t = blockIdx.x * blockDim.x + threadIdx.x;
    if (t < n_nodes) g_deg[t] = 0.0f;
    if (t < GG * HH) g_pooled[t] = 0.0f;
    if (t < GG) g_cnt[t] = 0.0f;
}

// ---------------------------------------------------------------------------
// deg[dst] += w  (edge parallel)
// ---------------------------------------------------------------------------
__global__ void deg_kernel(const int* __restrict__ dst, const float* __restrict__ w, int E) {
    int e = blockIdx.x * blockDim.x + threadIdx.x;
    if (e < E) atomicAdd(&g_deg[dst[e]], w[e]);
}

// dinv = rsqrt(deg + 2); selfc = 2 * dinv^2
__global__ void dinv_kernel(int n_nodes) {
    int i = blockIdx.x * blockDim.x + threadIdx.x;
    if (i < n_nodes) {
        float d = g_deg[i] + 2.0f;
        float di = rsqrtf(d);
        g_dinv[i] = di;
        g_selfc[i] = 2.0f * di * di;
    }
}

// norm[e] = dinv[src] * w * dinv[dst]
__global__ void norm_kernel(const int* __restrict__ src, const int* __restrict__ dst,
                            const float* __restrict__ w, int E) {
    int e = blockIdx.x * blockDim.x + threadIdx.x;
    if (e < E) g_norm[e] = g_dinv[src[e]] * w[e] * g_dinv[dst[e]];
}

// ---------------------------------------------------------------------------
// GEMM: g_xw = act(in) @ W ; g_h = b + selfc * xw  (self-loop + bias fused)
// in == nullptr means "read g_h" (layers 2,3). In-place safe: each block
// reads its 128 rows into SMEM before writing them; no cross-row deps.
// Block: 256 threads, 128 rows. Thread tile: 16 rows x 2 cols.
// SMEM: W (16KB) + input tile 128x64 (32KB) = 48KB.
// ---------------------------------------------------------------------------
__global__ __launch_bounds__(256) void gemm_kernel(
    const float* in, const float* __restrict__ W, const float* __restrict__ b,
    int n_rows, int relu_in)
{
    __shared__ float Ws[HH * HH];       // [k][c]
    __shared__ float Hs[128][HH];       // [r][k]

    const float* src_in = (in == nullptr) ? g_h : in;

    int tid = threadIdx.x;
    int row0 = blockIdx.x * 128;

    for (int i = tid; i < HH * HH; i += 256) Ws[i] = W[i];

    for (int i = tid; i < 128 * 16; i += 256) {
        int r = i >> 4;
        int c4 = i & 15;
        int grow = row0 + r;
        float4 v = make_float4(0.f, 0.f, 0.f, 0.f);
        if (grow < n_rows) v = ((const float4*)src_in)[grow * 16 + c4];
        if (relu_in) {
            v.x = fmaxf(v.x, 0.f); v.y = fmaxf(v.y, 0.f);
            v.z = fmaxf(v.z, 0.f); v.w = fmaxf(v.w, 0.f);
        }
        Hs[r][c4 * 4 + 0] = v.x;
        Hs[r][c4 * 4 + 1] = v.y;
        Hs[r][c4 * 4 + 2] = v.z;
        Hs[r][c4 * 4 + 3] = v.w;
    }
    __syncthreads();

    int tx = tid & 31;            // output col (tx and tx+32)
    int ty = tid >> 5;            // row group (16 rows each)
    int rbase = ty * 16;

    float acc0[16];
    float acc1[16];
    #pragma unroll
    for (int r = 0; r < 16; r++) { acc0[r] = 0.f; acc1[r] = 0.f; }

    #pragma unroll 8
    for (int k = 0; k < HH; k++) {
        float w0 = Ws[k * HH + tx];
        float w1 = Ws[k * HH + tx + 32];
        #pragma unroll
        for (int r = 0; r < 16; r++) {
            float hv = Hs[rbase + r][k];   // warp-uniform -> smem broadcast
            acc0[r] += hv * w0;
            acc1[r] += hv * w1;
        }
    }

    float b0 = b[tx];
    float b1 = b[tx + 32];
    #pragma unroll
    for (int r = 0; r < 16; r++) {
        int grow = row0 + rbase + r;
        if (grow < n_rows) {
            float sc = g_selfc[grow];
            g_xw[grow * HH + tx]      = acc0[r];
            g_xw[grow * HH + tx + 32] = acc1[r];
            g_h[grow * HH + tx]       = b0 + sc * acc0[r];
            g_h[grow * HH + tx + 32]  = b1 + sc * acc1[r];
        }
    }
}

// ---------------------------------------------------------------------------
// Scatter: g_h[dst] += norm[e] * g_xw[src]. 16 lanes per edge, float4 + red.v4
// ---------------------------------------------------------------------------
__global__ __launch_bounds__(256) void scatter_kernel(
    const int* __restrict__ src, const int* __restrict__ dst, int E)
{
    int t = blockIdx.x * blockDim.x + threadIdx.x;
    int e = t >> 4;
    if (e >= E) return;
    int lane = t & 15;
    int s = src[e];
    int d = dst[e];
    float nm = g_norm[e];
    float4 v = ((const float4*)g_xw)[s * 16 + lane];
    float rx = v.x * nm, ry = v.y * nm, rz = v.z * nm, rw = v.w * nm;
    float* p = g_h + d * HH + lane * 4;
    asm volatile("red.global.add.v4.f32 [%0], {%1, %2, %3, %4};"
                 :: "l"(p), "f"(rx), "f"(ry), "f"(rz), "f"(rw) : "memory");
}

// ---------------------------------------------------------------------------
// Pool: pooled[batch[i]] += g_h[i]; cnt[batch[i]] += 1
// ---------------------------------------------------------------------------
__global__ __launch_bounds__(256) void pool_kernel(
    const int* __restrict__ batch, int n_nodes)
{
    int t = blockIdx.x * blockDim.x + threadIdx.x;
    int i = t >> 4;
    if (i >= n_nodes) return;
    int lane = t & 15;
    int g = batch[i];
    float4 v = ((const float4*)g_h)[i * 16 + lane];
    float* p = g_pooled + g * HH + lane * 4;
    asm volatile("red.global.add.v4.f32 [%0], {%1, %2, %3, %4};"
                 :: "l"(p), "f"(v.x), "f"(v.y), "f"(v.z), "f"(v.w) : "memory");
    if (lane == 0) atomicAdd(&g_cnt[g], 1.0f);
}

// ---------------------------------------------------------------------------
// Head: out[g][c] = (pooled[g]/cnt[g]) @ Wl + bl
// ---------------------------------------------------------------------------
__global__ void final_kernel(const float* __restrict__ Wl, const float* __restrict__ bl,
                             float* __restrict__ out)
{
    int t = blockIdx.x * blockDim.x + threadIdx.x;
    if (t >= GG * CC) return;
    int g = t >> 1;
    int c = t & 1;
    float inv = 1.0f / fmaxf(g_cnt[g], 1.0f);
    float s = 0.0f;
    #pragma unroll
    for (int k = 0; k < HH; k++) s += g_pooled[g * HH + k] * Wl[k * CC + c];
    out[t] = s * inv + bl[c];
}

// ---------------------------------------------------------------------------
extern "C" void kernel_launch(void* const* d_in, const int* in_sizes, int n_in,
                              void* d_out, int out_size)
{
    const float* x     = (const float*)d_in[0];
    const int*   ei    = (const int*)d_in[1];     // [2, E] row-major: src then dst
    const float* eattr = (const float*)d_in[2];
    const int*   batch = (const int*)d_in[3];
    const float* W1 = (const float*)d_in[4];
    const float* b1 = (const float*)d_in[5];
    const float* W2 = (const float*)d_in[6];
    const float* b2 = (const float*)d_in[7];
    const float* W3 = (const float*)d_in[8];
    const float* b3 = (const float*)d_in[9];
    const float* Wl = (const float*)d_in[10];
    const float* bl = (const float*)d_in[11];
    float* out = (float*)d_out;

    int N = in_sizes[0] / HH;
    int E = in_sizes[2];
    const int* src = ei;
    const int* dst = ei + E;

    int nb256 = (N + 255) / 256;
    int eb256 = (E + 255) / 256;
    int gemm_blocks = (N + 127) / 128;
    int scat_blocks = (E * 16 + 255) / 256;
    int pool_blocks = (N * 16 + 255) / 256;

    // Precompute (identical across layers: edge weights are layer-invariant)
    init_kernel<<<nb256, 256>>>(N);
    deg_kernel<<<eb256, 256>>>(dst, eattr, E);
    dinv_kernel<<<nb256, 256>>>(N);
    norm_kernel<<<eb256, 256>>>(src, dst, eattr, E);

    // Layer 1 (input x, no relu on input)
    gemm_kernel<<<gemm_blocks, 256>>>(x, W1, b1, N, 0);
    scatter_kernel<<<scat_blocks, 256>>>(src, dst, E);

    // Layer 2 (input g_h, relu fused into tile load)
    gemm_kernel<<<gemm_blocks, 256>>>(nullptr, W2, b2, N, 1);
    scatter_kernel<<<scat_blocks, 256>>>(src, dst, E);

    // Layer 3
    gemm_kernel<<<gemm_blocks, 256>>>(nullptr, W3, b3, N, 1);
    scatter_kernel<<<scat_blocks, 256>>>(src, dst, E);

    // Pool + head
    pool_kernel<<<pool_blocks, 256>>>(batch, N);
    final_kernel<<<(GG * CC + 255) / 256, 256>>>(Wl, bl, out);
}